// round 2
// baseline (speedup 1.0000x reference)
#include <cuda_runtime.h>

#define D_ 16
#define K_ 64
#define WARPS_ 16
#define BLOCK_ (WARPS_ * 32)
#define GRID_ 148
#define MAXB_ 160
#define ILP_ 8

// dynamic smem bytes: per warp: s(64*16*4) + s2(64*16*4) + cnt(64*4) + si(64*8) + si2(64*8)
#define SMEM_BYTES_ (WARPS_ * (K_*D_*4*2 + K_*4 + K_*8*2))

__device__ int g_lab_stride;

__device__ float  g_s  [MAXB_][K_*D_];
__device__ float  g_s2 [MAXB_][K_*D_];
__device__ float  g_cnt[MAXB_][K_];
__device__ double g_si [MAXB_][K_];
__device__ double g_si2[MAXB_][K_];

// Detect whether labels are serialized as int32 (stride 1) or int64 (stride 2).
// int64 little-endian high words of values in [0,64) are all zero; int32 odd
// elements are labels (nonzero with p=63/64 each, 64 samples => certainty).
__global__ void detect_kernel(const int* __restrict__ lab32, int n) {
    __shared__ int flag;
    if (threadIdx.x == 0) flag = 0;
    __syncthreads();
    int t = threadIdx.x;           // 64 threads
    int idx = 2 * t + 1;           // always << n
    if (idx < n && lab32[idx] != 0) atomicExch(&flag, 1);
    __syncthreads();
    if (t == 0) g_lab_stride = flag ? 1 : 2;
}

__global__ void __launch_bounds__(BLOCK_)
accum_kernel(const float* __restrict__ data, const int* __restrict__ lab32, int N) {
    extern __shared__ unsigned char smraw[];
    float*  sS   = (float*)smraw;                 // [WARPS_][K_*D_]
    float*  sS2  = sS  + WARPS_ * K_ * D_;        // [WARPS_][K_*D_]
    float*  sCnt = sS2 + WARPS_ * K_ * D_;        // [WARPS_][K_]
    double* sSi  = (double*)(sCnt + WARPS_ * K_); // [WARPS_][K_]
    double* sSi2 = sSi + WARPS_ * K_;             // [WARPS_][K_]

    const int tid    = threadIdx.x;
    const int warpId = tid >> 5;
    const int lane   = tid & 31;

    for (int i = tid; i < WARPS_ * K_ * D_; i += BLOCK_) { sS[i] = 0.f; sS2[i] = 0.f; }
    for (int i = tid; i < WARPS_ * K_;      i += BLOCK_) { sCnt[i] = 0.f; sSi[i] = 0.0; sSi2[i] = 0.0; }
    __syncthreads();

    const int ls = g_lab_stride;            // 1 (int32) or 2 (int64 low word)
    const int P  = N >> 1;                  // row pairs
    const int gw   = blockIdx.x * WARPS_ + warpId;
    const int totW = gridDim.x * WARPS_;
    const int f    = lane & 15;
    const int half = lane >> 4;

    float*  mS   = sS   + warpId * K_ * D_;
    float*  mS2  = sS2  + warpId * K_ * D_;
    float*  mC   = sCnt + warpId * K_;
    double* mSi  = sSi  + warpId * K_;
    double* mSi2 = sSi2 + warpId * K_;

    // per-lane label pointer: row = 2*p + half, elem index = row * ls
    const int* labp = lab32 + (long long)half * ls;
    const long long labStep = 2LL * ls;     // per +1 pair

    for (long long base = (long long)gw * ILP_; base < P; base += (long long)totW * ILP_) {
        float v[ILP_]; int g[ILP_]; int valid[ILP_];
        const float* dp = data + base * 32 + lane;
        const int*   lp = labp + base * labStep;
        #pragma unroll
        for (int j = 0; j < ILP_; j++) {
            long long p = base + j;
            valid[j] = (p < P);
            if (valid[j]) {
                v[j] = dp[(long long)j * 32];               // 2 rows = 128B coalesced
                g[j] = lp[(long long)j * labStep];
            } else { v[j] = 0.f; g[j] = 0; }
        }
        #pragma unroll
        for (int j = 0; j < ILP_; j++) {
            if (!valid[j]) continue;                        // warp-uniform guard
            float x  = v[j];
            float xs = x * x;
            int   gg = g[j];
            int   go  = __shfl_xor_sync(0xffffffffu, gg, 16);
            float xo  = __shfl_xor_sync(0xffffffffu, x,  16);
            float xso = __shfl_xor_sync(0xffffffffu, xs, 16);
            bool same = (gg == go);
            if (same) { x += xo; xs += xso; }               // fold colliding pair
            if (!same || lane < 16) {                       // distinct (g,f) per lane
                int idx = gg * D_ + f;
                mS [idx] += x;                              // plain smem RMW, no atomics
                mS2[idx] += xs;
            }
            if (lane == 0 || (lane == 16 && !same)) {       // per-row scalar stats
                long long p = base + j;
                double r  = (double)(2 * p + half);
                double si = r, si2 = r * r;
                float  c  = 1.f;
                if (same) { double r2 = r + 1.0; si += r2; si2 += r2 * r2; c = 2.f; }
                mC  [gg] += c;
                mSi [gg] += si;
                mSi2[gg] += si2;
            }
        }
    }

    // odd-N tail row (not hit for N = 2M, kept for safety)
    if ((N & 1) && blockIdx.x == 0 && warpId == 0 && lane < 16) {
        long long r = N - 1;
        float x = data[r * 16 + lane];
        int  gg = lab32[r * ls];
        mS [gg * D_ + f] += x;
        mS2[gg * D_ + f] += x * x;
        if (lane == 0) { mC[gg] += 1.f; mSi[gg] += (double)r; mSi2[gg] += (double)r * (double)r; }
    }
    __syncthreads();

    // reduce the 16 warp-copies -> per-block scratch (deterministic, no atomics)
    for (int c = tid; c < K_ * D_; c += BLOCK_) {
        float a = 0.f, b = 0.f;
        #pragma unroll
        for (int w = 0; w < WARPS_; w++) { a += sS[w * K_ * D_ + c]; b += sS2[w * K_ * D_ + c]; }
        g_s [blockIdx.x][c] = a;
        g_s2[blockIdx.x][c] = b;
    }
    for (int c = tid; c < K_; c += BLOCK_) {
        float a = 0.f; double si = 0.0, si2 = 0.0;
        #pragma unroll
        for (int w = 0; w < WARPS_; w++) { a += sCnt[w * K_ + c]; si += sSi[w * K_ + c]; si2 += sSi2[w * K_ + c]; }
        g_cnt[blockIdx.x][c] = a;
        g_si [blockIdx.x][c] = si;
        g_si2[blockIdx.x][c] = si2;
    }
}

__global__ void __launch_bounds__(1024)
finalize_kernel(float* __restrict__ out, int nb) {
    __shared__ float  rs[K_*D_], rs2[K_*D_];
    __shared__ float  rc[K_];
    __shared__ double rsi[K_], rsi2[K_];
    __shared__ double gl[K_];
    int t = threadIdx.x;

    if (t < K_ * D_) {
        float a = 0.f, b = 0.f;
        for (int bI = 0; bI < nb; bI++) { a += g_s[bI][t]; b += g_s2[bI][t]; }
        rs[t] = a; rs2[t] = b;
    }
    if (t < K_) {
        float c = 0.f; double si = 0.0, si2 = 0.0;
        for (int bI = 0; bI < nb; bI++) { c += g_cnt[bI][t]; si += g_si[bI][t]; si2 += g_si2[bI][t]; }
        rc[t] = c; rsi[t] = si; rsi2[t] = si2;
    }
    __syncthreads();

    if (t < K_) {
        double count = (double)rc[t];
        double cnt   = fmax(count, 1.0);
        double sse = 0.0;
        #pragma unroll
        for (int fI = 0; fI < D_; fI++) {
            double s  = (double)rs [t * D_ + fI];
            double s2 = (double)rs2[t * D_ + fI];
            sse += s2 - s * s / cnt;
        }
        double loss2 = sse / cnt;
        double mi   = rsi[t] / cnt;
        double var  = (rsi2[t] - cnt * mi * mi) / fmax(cnt - 1.0, 1.0);
        double stdi = sqrt(fmax(var, 0.0));
        double mstd = sqrt(cnt * (cnt + 1.0) / 12.0);
        double loss1 = (stdi - mstd) / cnt;
        gl[t] = (count > 0.0) ? (0.1 * loss1 + loss2) : 0.0;
    }
    __syncthreads();
    if (t == 0) {
        double s = 0.0;
        for (int i = 0; i < K_; i++) s += gl[i];
        out[0] = (float)s;
    }
}

extern "C" void kernel_launch(void* const* d_in, const int* in_sizes, int n_in,
                              void* d_out, int out_size) {
    const float* data  = (const float*)d_in[0];
    const int*   lab32 = (const int*)d_in[1];
    int N = in_sizes[0] / D_;

    cudaFuncSetAttribute(accum_kernel, cudaFuncAttributeMaxDynamicSharedMemorySize, SMEM_BYTES_);

    detect_kernel<<<1, 64>>>(lab32, in_sizes[1]);
    accum_kernel<<<GRID_, BLOCK_, SMEM_BYTES_>>>(data, lab32, N);
    finalize_kernel<<<1, 1024>>>((float*)d_out, GRID_);
}

// round 5
// speedup vs baseline: 1.3815x; 1.3815x over previous
#include <cuda_runtime.h>

#define D_ 16
#define K_ 64
#define WARPS_ 12
#define BLOCK_ (WARPS_ * 32)
#define GRID_ 148
#define ILP_ 8

// per-warp smem: vec float2[K][2][D] = 16KB ; scalar u64[K][2][2] = 2KB
#define VEC_PER_WARP_   (K_ * 2 * D_)          // float2 elements (2048)
#define SCAL_PER_WARP_  (K_ * 2 * 2)           // u64 elements (256)
#define SMEM_BYTES_ (WARPS_ * (VEC_PER_WARP_ * 8 + SCAL_PER_WARP_ * 8))  // 221,184 B

#define CNT_SHIFT_ 42
#define SI_MASK_   ((1ULL << CNT_SHIFT_) - 1ULL)

__device__ float2             g_vec [GRID_][K_ * D_];   // per-block (g,f) sums {S, S2}
__device__ unsigned long long g_scal[GRID_][K_ * 2];    // per-block per-g {packed(cnt|si), si2}
__device__ double             g_gl[K_];
__device__ int                g_arrive = 0;

template<int LS>
__device__ __forceinline__ void mainloop(
    const float* __restrict__ data, const int* __restrict__ lab,
    long long P, int gw, int totW,
    float2* __restrict__ mVec, unsigned long long* __restrict__ mScal,
    int lane, int half)
{
    const bool doScal = ((lane & 14) == 0);      // lanes 0,1,16,17
    const int  kSel   = lane & 1;                // 0: packed cnt|si, 1: si2
    const int  sOff   = half * 2 + kSel;
    const long long step = (long long)totW * ILP_;
    long long base = (long long)gw * ILP_;

    for (; base + ILP_ <= P; base += step) {
        const float* dp = data + base * 32 + lane;
        const int*   lp = lab + (2 * base + half) * LS;
        float v[ILP_]; int gg[ILP_];
        #pragma unroll
        for (int j = 0; j < ILP_; j++) { v[j] = dp[j * 32]; gg[j] = lp[j * 2 * LS]; }
        const unsigned rbase = (unsigned)(2 * base) + (unsigned)half;
        #pragma unroll
        for (int j = 0; j < ILP_; j++) {
            float x = v[j], xs = x * x;
            int idx = gg[j] * 32 + lane;          // [g][half][f], conflict-free
            float2 a = mVec[idx];
            a.x += x; a.y += xs;
            mVec[idx] = a;
            if (doScal) {
                unsigned r = rbase + 2u * (unsigned)j;
                unsigned long long add = kSel ? (unsigned long long)r * r
                                              : ((unsigned long long)r | (1ULL << CNT_SHIFT_));
                mScal[gg[j] * 4 + sOff] += add;
            }
        }
    }
    // tail (partial final iteration)
    {
        const float* dp = data + base * 32 + lane;
        const int*   lp = lab + (2 * base + half) * LS;
        #pragma unroll
        for (int j = 0; j < ILP_; j++) {
            if (base + j < P) {
                float x = dp[j * 32]; int g = lp[j * 2 * LS];
                float xs = x * x;
                int idx = g * 32 + lane;
                float2 a = mVec[idx]; a.x += x; a.y += xs; mVec[idx] = a;
                if (doScal) {
                    unsigned r = (unsigned)(2 * (base + j)) + (unsigned)half;
                    unsigned long long add = kSel ? (unsigned long long)r * r
                                                  : ((unsigned long long)r | (1ULL << CNT_SHIFT_));
                    mScal[g * 4 + sOff] += add;
                }
            }
        }
    }
}

__global__ void __launch_bounds__(BLOCK_)
accum_kernel(const float* __restrict__ data, const int* __restrict__ lab32, int N) {
    extern __shared__ unsigned char smraw[];
    float2*             sVec  = (float2*)smraw;                          // [WARPS_][2048]
    unsigned long long* sScal = (unsigned long long*)(sVec + WARPS_ * VEC_PER_WARP_); // [WARPS_][256]

    const int tid    = threadIdx.x;
    const int warpId = tid >> 5;
    const int lane   = tid & 31;
    const int half   = lane >> 4;

    // ---- label-stride detection (int64 little-endian high words all zero) ----
    __shared__ int s_ls;
    if (warpId == 0) {
        int a = lab32[2 * lane + 1] | lab32[2 * lane + 65];
        int any = __any_sync(0xffffffffu, a != 0);
        if (lane == 0) s_ls = any ? 1 : 2;
    }

    // ---- zero smem ----
    {
        float4* z = (float4*)smraw;
        const int nz = SMEM_BYTES_ / 16;
        for (int i = tid; i < nz; i += BLOCK_) z[i] = make_float4(0.f, 0.f, 0.f, 0.f);
    }
    __syncthreads();

    const int ls = s_ls;
    const long long P = (long long)(N >> 1);
    const int gw   = blockIdx.x * WARPS_ + warpId;
    const int totW = GRID_ * WARPS_;

    float2*             mVec  = sVec  + warpId * VEC_PER_WARP_;
    unsigned long long* mScal = sScal + warpId * SCAL_PER_WARP_;

    if (ls == 1) mainloop<1>(data, lab32, P, gw, totW, mVec, mScal, lane, half);
    else         mainloop<2>(data, lab32, P, gw, totW, mVec, mScal, lane, half);

    // odd-N last row (not hit for N=2M)
    if ((N & 1) && blockIdx.x == 0 && warpId == 0) {
        long long r = N - 1;
        int g = lab32[r * ls];
        if (lane < 16) {
            float x = data[r * 16 + lane];
            int idx = g * 32 + lane;
            float2 a = mVec[idx]; a.x += x; a.y += x * x; mVec[idx] = a;
        }
        if (lane == 0) mScal[g * 4 + 0] += ((unsigned long long)r | (1ULL << CNT_SHIFT_));
        if (lane == 1) mScal[g * 4 + 1] += (unsigned long long)r * (unsigned long long)r;
    }
    __syncthreads();

    // ---- drain: reduce warp copies (and halves) -> per-block global scratch ----
    for (int i = tid; i < K_ * D_; i += BLOCK_) {
        int g = i >> 4, f = i & 15;
        float2 s = make_float2(0.f, 0.f);
        #pragma unroll
        for (int w = 0; w < WARPS_; w++) {
            float2 a = sVec[w * VEC_PER_WARP_ + g * 32 + f];
            float2 b = sVec[w * VEC_PER_WARP_ + g * 32 + 16 + f];
            s.x += a.x + b.x; s.y += a.y + b.y;
        }
        g_vec[blockIdx.x][i] = s;
    }
    for (int i = tid; i < K_ * 2; i += BLOCK_) {
        int g = i >> 1, k = i & 1;
        unsigned long long s = 0ULL;
        #pragma unroll
        for (int w = 0; w < WARPS_; w++)
            s += sScal[w * SCAL_PER_WARP_ + g * 4 + k]
               + sScal[w * SCAL_PER_WARP_ + g * 4 + 2 + k];
        g_scal[blockIdx.x][i] = s;
    }
}

__global__ void __launch_bounds__(512)
finalize_kernel(float* __restrict__ out) {
    const int g    = blockIdx.x;          // one block per group
    const int w    = threadIdx.x >> 5;    // warp = feature
    const int lane = threadIdx.x & 31;
    __shared__ float  sS[D_], sS2[D_];
    __shared__ unsigned long long sPk, sI2;

    // feature sums over blocks
    {
        float a = 0.f, b = 0.f;
        for (int bI = lane; bI < GRID_; bI += 32) {
            float2 v = g_vec[bI][g * D_ + w];
            a += v.x; b += v.y;
        }
        #pragma unroll
        for (int o = 16; o; o >>= 1) {
            a += __shfl_xor_sync(0xffffffffu, a, o);
            b += __shfl_xor_sync(0xffffffffu, b, o);
        }
        if (lane == 0) { sS[w] = a; sS2[w] = b; }
    }
    // scalar sums over blocks (warps 0 and 1 redo in u64)
    if (w < 2) {
        unsigned long long s = 0ULL;
        for (int bI = lane; bI < GRID_; bI += 32) s += g_scal[bI][g * 2 + w];
        #pragma unroll
        for (int o = 16; o; o >>= 1) s += __shfl_xor_sync(0xffffffffu, s, o);
        if (lane == 0) { if (w == 0) sPk = s; else sI2 = s; }
    }
    __syncthreads();

    if (threadIdx.x == 0) {
        unsigned long long packed = sPk;
        double count = (double)(packed >> CNT_SHIFT_);
        double si    = (double)(packed & SI_MASK_);
        double si2   = (double)sI2;
        double cnt   = fmax(count, 1.0);

        double sse = 0.0;
        #pragma unroll
        for (int f = 0; f < D_; f++) {
            double s = (double)sS[f];
            sse += (double)sS2[f] - s * s / cnt;
        }
        double loss2 = sse / cnt;
        double mi   = si / cnt;
        double var  = (si2 - cnt * mi * mi) / fmax(cnt - 1.0, 1.0);
        double stdi = sqrt(fmax(var, 0.0));
        double mstd = sqrt(cnt * (cnt + 1.0) / 12.0);
        double loss1 = (stdi - mstd) / cnt;
        g_gl[g] = (count > 0.0) ? (0.1 * loss1 + loss2) : 0.0;

        __threadfence();
        if (atomicAdd(&g_arrive, 1) == K_ - 1) {
            __threadfence();
            double s = 0.0;
            #pragma unroll
            for (int i = 0; i < K_; i++) s += g_gl[i];
            out[0] = (float)s;
            g_arrive = 0;                 // reset for next graph replay
        }
    }
}

extern "C" void kernel_launch(void* const* d_in, const int* in_sizes, int n_in,
                              void* d_out, int out_size) {
    const float* data  = (const float*)d_in[0];
    const int*   lab32 = (const int*)d_in[1];
    int N = in_sizes[0] / D_;

    cudaFuncSetAttribute(accum_kernel, cudaFuncAttributeMaxDynamicSharedMemorySize, SMEM_BYTES_);

    accum_kernel<<<GRID_, BLOCK_, SMEM_BYTES_>>>(data, lab32, N);
    finalize_kernel<<<K_, 512>>>((float*)d_out);
}